// round 16
// baseline (speedup 1.0000x reference)
#include <cuda_runtime.h>
#include <cuda_fp16.h>
#include <cstdint>

// Problem constants
#define BSZ 8
#define SEQ 1024
#define NX  1024
#define NH  16
#define HD  64

// All half-precision buffers stored as uint32 words (2 halves per word)
__device__ uint32_t b_inq[8192 * 512];   // query, fp16
__device__ uint32_t b_inx[8192 * 512];   // x, fp16
__device__ uint32_t b_w2[512 * 3072];    // attw packed: [k2][n], word=(k even, k odd)
__device__ uint32_t b_p2[512 * 1024];    // projw packed
__device__ uint32_t b_q[8192 * 512];     // q*0.125, fp16
__device__ uint32_t b_k[8192 * 512];
__device__ uint32_t b_v[8192 * 512];
__device__ uint32_t b_a[8192 * 512];     // attention out, fp16

// ---------------------------------------------------------------------------
// helpers
// ---------------------------------------------------------------------------
__device__ __forceinline__ uint32_t pack_h2(float lo, float hi) {
    uint32_t d;
    asm("cvt.rn.f16x2.f32 %0, %1, %2;" : "=r"(d) : "f"(hi), "f"(lo));
    return d;
}
__device__ __forceinline__ void mma_f16(float c[4], const uint32_t a[4],
                                        const uint32_t b[2]) {
    asm volatile(
        "mma.sync.aligned.m16n8k16.row.col.f32.f16.f16.f32 "
        "{%0,%1,%2,%3}, {%4,%5,%6,%7}, {%8,%9}, {%0,%1,%2,%3};\n"
        : "+f"(c[0]), "+f"(c[1]), "+f"(c[2]), "+f"(c[3])
        : "r"(a[0]), "r"(a[1]), "r"(a[2]), "r"(a[3]), "r"(b[0]), "r"(b[1]));
}
__device__ __forceinline__ void ldmatrix_x4(uint32_t r[4], uint32_t addr) {
    asm volatile("ldmatrix.sync.aligned.m8n8.x4.shared.b16 {%0,%1,%2,%3}, [%4];"
                 : "=r"(r[0]), "=r"(r[1]), "=r"(r[2]), "=r"(r[3]) : "r"(addr));
}
__device__ __forceinline__ void ldmatrix_x4t(uint32_t r[4], uint32_t addr) {
    asm volatile("ldmatrix.sync.aligned.m8n8.x4.trans.shared.b16 {%0,%1,%2,%3}, [%4];"
                 : "=r"(r[0]), "=r"(r[1]), "=r"(r[2]), "=r"(r[3]) : "r"(addr));
}
__device__ __forceinline__ void cpa16(uint32_t dst, const void* src) {
    asm volatile("cp.async.cg.shared.global [%0], [%1], 16;" :: "r"(dst), "l"(src));
}
__device__ __forceinline__ uint32_t smem_u32(const void* p) {
    uint32_t a;
    asm("{ .reg .u64 t; cvta.to.shared.u64 t, %1; cvt.u32.u64 %0, t; }"
        : "=r"(a) : "l"(p));
    return a;
}

// ---------------------------------------------------------------------------
// fused pre-pass: fp16 convert (q, x) + weight pack (attw, projw)
// conv: 4096 blocks (4 float4/thread); attw pack: 1536; projw pack: 512.
// ---------------------------------------------------------------------------
__global__ __launch_bounds__(256) void prepass_kernel(
    const float4* __restrict__ q, const float4* __restrict__ x,
    const float* __restrict__ attw, const float* __restrict__ projw)
{
    const int blk = blockIdx.x;
    const int tid = threadIdx.x;
    if (blk < 4096) {
        const bool isq = blk < 2048;
        const size_t base = (size_t)(isq ? blk : blk - 2048) * 1024;
        const float4* src = isq ? q : x;
        uint32_t* o = isq ? b_inq : b_inx;
#pragma unroll
        for (int rr = 0; rr < 4; ++rr) {
            const size_t i = base + tid + rr * 256;
            const float4 f = src[i];
            o[2 * i]     = pack_h2(f.x, f.y);
            o[2 * i + 1] = pack_h2(f.z, f.w);
        }
    } else if (blk < 5632) {
        const int idx = blk - 4096;
        const int n4 = (idx % 3) * 256 + tid;
        const int k2 = idx / 3;
        const float4 e = *(const float4*)(attw + (size_t)(2 * k2) * 3072 + 4 * n4);
        const float4 o = *(const float4*)(attw + (size_t)(2 * k2 + 1) * 3072 + 4 * n4);
        uint4 r;
        r.x = pack_h2(e.x, o.x); r.y = pack_h2(e.y, o.y);
        r.z = pack_h2(e.z, o.z); r.w = pack_h2(e.w, o.w);
        *(uint4*)(b_w2 + (size_t)k2 * 3072 + 4 * n4) = r;
    } else {
        const int k2 = blk - 5632;
        const int n4 = tid;
        const float4 e = *(const float4*)(projw + (size_t)(2 * k2) * 1024 + 4 * n4);
        const float4 o = *(const float4*)(projw + (size_t)(2 * k2 + 1) * 1024 + 4 * n4);
        uint4 r;
        r.x = pack_h2(e.x, o.x); r.y = pack_h2(e.y, o.y);
        r.z = pack_h2(e.z, o.z); r.w = pack_h2(e.w, o.w);
        *(uint4*)(b_p2 + (size_t)k2 * 1024 + 4 * n4) = r;
    }
}

// ---------------------------------------------------------------------------
// fp16 GEMM mainloop: CTA 128x128, 256 thr = 8 warps (2m x 4n), warp 64x32.
// 3-stage cp.async pipeline (wait_group 1), ldmatrix.x4 A fragments.
// ---------------------------------------------------------------------------
#define AW 36
#define BW 136
#define STW (128 * AW + 32 * BW)          // words per stage = 8960
#define NST 3
#define GEMM_DYN (NST * STW * 4)          // 107520 bytes

__device__ __forceinline__ void gemm16_main(
    const uint32_t* __restrict__ Ag, const uint32_t* __restrict__ Wg,
    int ldw2, int m0, int ng, float acc[4][4][4])
{
    extern __shared__ __align__(16) uint32_t smw[];
    const uint32_t sbase = smem_u32(smw);

    const int t = threadIdx.x;
    const int lane = t & 31;
    const int warp = t >> 5;
    const int gid = lane >> 2, tg = lane & 3;
    const int wm = (warp & 1) * 64, wn = (warp >> 1) * 32;
    const int sr = t >> 3;
    const int si = (t & 7) * 4;

#pragma unroll
    for (int i = 0; i < 4; ++i)
#pragma unroll
        for (int j = 0; j < 4; ++j)
#pragma unroll
            for (int r = 0; r < 4; ++r) acc[i][j][r] = 0.0f;

    auto load_stage = [&](int kt, int st) {
        const uint32_t sa = sbase + (st * STW) * 4;
        const uint32_t sb = sa + (128 * AW) * 4;
#pragma unroll
        for (int rr = 0; rr < 4; ++rr)
            cpa16(sa + ((sr + rr * 32) * AW + si) * 4,
                  Ag + (size_t)(m0 + sr + rr * 32) * 512 + kt * 32 + si);
#pragma unroll
        for (int ii = 0; ii < 2; ++ii) {
            const int id = t + ii * 256;
            const int brow = id >> 5;
            const int bcol = (id & 31) * 4;
            cpa16(sb + (brow * BW + bcol) * 4,
                  Wg + (size_t)(kt * 32 + brow) * ldw2 + ng + bcol);
        }
#pragma unroll
        for (int ii = 0; ii < 2; ++ii) {
            const int id = t + ii * 256;
            const int brow = (id >> 5) + 16;
            const int bcol = (id & 31) * 4;
            cpa16(sb + (brow * BW + bcol) * 4,
                  Wg + (size_t)(kt * 32 + brow) * ldw2 + ng + bcol);
        }
        asm volatile("cp.async.commit_group;" ::: "memory");
    };

    load_stage(0, 0);
    load_stage(1, 1);

    for (int kt = 0; kt < 16; ++kt) {
        const int cur = kt % NST;
        asm volatile("cp.async.wait_group 1;" ::: "memory");
        __syncthreads();
        if (kt + 2 < 16) load_stage(kt + 2, (kt + 2) % NST);

        const uint32_t sa = sbase + (cur * STW) * 4;
        const uint32_t* Bs = smw + cur * STW + 128 * AW;
        const uint32_t arow = (uint32_t)(lane & 15);
        const uint32_t ahalf = (uint32_t)(lane >> 4) * 4;

#pragma unroll
        for (int c = 0; c < 4; ++c) {
            uint32_t afr[4][4], bfr[4][2];
#pragma unroll
            for (int mf = 0; mf < 4; ++mf)
                ldmatrix_x4(afr[mf],
                    sa + ((wm + mf * 16 + arow) * AW + c * 8 + ahalf) * 4);
#pragma unroll
            for (int nf = 0; nf < 4; ++nf) {
                const int n = wn + nf * 8 + gid;
                bfr[nf][0] = Bs[(c * 8 + tg) * BW + n];
                bfr[nf][1] = Bs[(c * 8 + tg + 4) * BW + n];
            }
#pragma unroll
            for (int mf = 0; mf < 4; ++mf)
#pragma unroll
                for (int nf = 0; nf < 4; ++nf)
                    mma_f16(acc[mf][nf], afr[mf], bfr[nf]);
        }
    }
}

// qkv projection: grid (24, 64). Writes q/k/v as fp16 (q pre-scaled 0.125).
__global__ __launch_bounds__(256) void qkv_gemm_kernel(const float* __restrict__ bias)
{
    const int ng = blockIdx.x * 128;
    const int m0 = blockIdx.y * 128;
    const uint32_t* Ag = (ng < 1024) ? b_inq : b_inx;
    float acc[4][4][4];
    gemm16_main(Ag, b_w2, 3072, m0, ng, acc);

    const int t = threadIdx.x;
    const int lane = t & 31, warp = t >> 5;
    const int gid = lane >> 2, tg = lane & 3;
    const int wm = (warp & 1) * 64, wn = (warp >> 1) * 32;

    uint32_t* Og; int ccol; float scale;
    if (ng < 1024)       { Og = b_q; ccol = ng;        scale = 0.125f; }
    else if (ng < 2048)  { Og = b_k; ccol = ng - 1024; scale = 1.0f; }
    else                 { Og = b_v; ccol = ng - 2048; scale = 1.0f; }

#pragma unroll
    for (int nf = 0; nf < 4; ++nf) {
        const int cl = wn + nf * 8 + 2 * tg;
        const float b0 = bias[ng + cl], b1 = bias[ng + cl + 1];
#pragma unroll
        for (int mf = 0; mf < 4; ++mf) {
            const int row = m0 + wm + mf * 16 + gid;
            Og[(size_t)row * 512 + (ccol + cl) / 2] =
                pack_h2((acc[mf][nf][0] + b0) * scale,
                        (acc[mf][nf][1] + b1) * scale);
            Og[(size_t)(row + 8) * 512 + (ccol + cl) / 2] =
                pack_h2((acc[mf][nf][2] + b0) * scale,
                        (acc[mf][nf][3] + b1) * scale);
        }
    }
}

// output projection: grid (8, 64). Reads b_a (fp16), writes f32 out.
__global__ __launch_bounds__(256) void proj_gemm_kernel(
    const float* __restrict__ bias, float* __restrict__ out)
{
    const int ng = blockIdx.x * 128;
    const int m0 = blockIdx.y * 128;
    float acc[4][4][4];
    gemm16_main(b_a, b_p2, 1024, m0, ng, acc);

    const int t = threadIdx.x;
    const int lane = t & 31, warp = t >> 5;
    const int gid = lane >> 2, tg = lane & 3;
    const int wm = (warp & 1) * 64, wn = (warp >> 1) * 32;

#pragma unroll
    for (int nf = 0; nf < 4; ++nf) {
        const int cl = wn + nf * 8 + 2 * tg;
        const float b0 = bias[ng + cl], b1 = bias[ng + cl + 1];
#pragma unroll
        for (int mf = 0; mf < 4; ++mf) {
            const int row = m0 + wm + mf * 16 + gid;
            *(float2*)(out + (size_t)row * 1024 + ng + cl) =
                make_float2(acc[mf][nf][0] + b0, acc[mf][nf][1] + b1);
            *(float2*)(out + (size_t)(row + 8) * 1024 + ng + cl) =
                make_float2(acc[mf][nf][2] + b0, acc[mf][nf][3] + b1);
        }
    }
}

// ---------------------------------------------------------------------------
// fp16 flash attention, 3-stage cp.async K/V pipeline.
// Grid (8, 16, 8), 256 thr (8 warps x 16 q-rows).
// Warp-skip: in block kb==2qb+1 warps 0..3 (rows 0..63) are fully masked
// (their contribution is exactly zero) -> skip their compute body entirely.
// ---------------------------------------------------------------------------
#define QW   (128 * 36)
#define KVW  (64 * 36)
#define ANST 3
#define ATT_DYN ((QW + ANST * 2 * KVW) * 4)   // 73728 bytes

__global__ __launch_bounds__(256) void attn_kernel()
{
    extern __shared__ __align__(16) uint32_t sma[];
    const uint32_t sbase = smem_u32(sma);

    const int qb = 7 - blockIdx.x;        // heavy tiles scheduled first
    const int h = blockIdx.y, b = blockIdx.z;
    const int t = threadIdx.x;
    const int warp = t >> 5, lane = t & 31;
    const int gid = lane >> 2, tg = lane & 3;
    const int r0 = warp * 16 + gid, r1 = r0 + 8;
    const size_t qrow0 = (size_t)(b * SEQ + qb * 128);
    const size_t kvbase = (size_t)(b * SEQ) * 512 + h * 32;

    auto load_kv = [&](int kb, int st) {
        const uint32_t kdst = sbase + (QW + st * 2 * KVW) * 4;
        const uint32_t vdst = kdst + KVW * 4;
#pragma unroll
        for (int i = 0; i < 2; ++i) {
            const int id = t + i * 256;
            const int row = id >> 3;
            const int cq = (id & 7) * 4;
            const size_t g = kvbase + (size_t)(kb * 64 + row) * 512 + cq;
            cpa16(kdst + (row * 36 + cq) * 4, b_k + g);
            cpa16(vdst + (row * 36 + cq) * 4, b_v + g);
        }
        asm volatile("cp.async.commit_group;" ::: "memory");
    };

    const int nkb = 2 * qb + 2;

    load_kv(0, 0);
    load_kv(1, 1);
    {
        const int sr = t >> 3, si = (t & 7) * 4;
#pragma unroll
        for (int rr = 0; rr < 4; ++rr) {
            uint4 v = *(const uint4*)(b_q + (qrow0 + sr + rr * 32) * 512
                                      + h * 32 + si);
            *(uint4*)&sma[(sr + rr * 32) * 36 + si] = v;
        }
    }
    __syncthreads();

    uint32_t qf[4][4];
#pragma unroll
    for (int c = 0; c < 4; ++c) {
        qf[c][0] = sma[r0 * 36 + c * 8 + tg];
        qf[c][1] = sma[r1 * 36 + c * 8 + tg];
        qf[c][2] = sma[r0 * 36 + c * 8 + tg + 4];
        qf[c][3] = sma[r1 * 36 + c * 8 + tg + 4];
    }

    float m_i[2] = {-3.0e38f, -3.0e38f};
    float l_i[2] = {0.0f, 0.0f};
    float O[8][4];
#pragma unroll
    for (int nf = 0; nf < 8; ++nf)
#pragma unroll
        for (int r = 0; r < 4; ++r) O[nf][r] = 0.0f;

    for (int kb = 0; kb < nkb; ++kb) {
        const int st = kb % ANST;
        if (kb + 1 < nkb)
            asm volatile("cp.async.wait_group 1;" ::: "memory");
        else
            asm volatile("cp.async.wait_group 0;" ::: "memory");
        __syncthreads();
        if (kb + 2 < nkb) load_kv(kb + 2, (kb + 2) % ANST);

        // Fully-masked block for rows 0..63: contribution is exactly zero.
        // (alpha would be 1, P would underflow to 0, l/O unchanged.)
        if (kb == 2 * qb + 1 && warp < 4) continue;

        const uint32_t* Ks = sma + QW + st * 2 * KVW;
        const uint32_t vbase = sbase + (QW + st * 2 * KVW + KVW) * 4;

        float s[8][4];
#pragma unroll
        for (int nf = 0; nf < 8; ++nf)
#pragma unroll
            for (int r = 0; r < 4; ++r) s[nf][r] = 0.0f;
#pragma unroll
        for (int c = 0; c < 4; ++c)
#pragma unroll
            for (int nf = 0; nf < 8; ++nf) {
                uint32_t bb[2];
                const int key = nf * 8 + gid;
                bb[0] = Ks[key * 36 + c * 8 + tg];
                bb[1] = Ks[key * 36 + c * 8 + tg + 4];
                mma_f16(s[nf], qf[c], bb);
            }

        if (kb >= 2 * qb) {
            const int grow0 = qb * 128 + r0;
            const int gcol0 = kb * 64 + 2 * tg;
#pragma unroll
            for (int nf = 0; nf < 8; ++nf) {
                int c = gcol0 + nf * 8;
                if (c     > grow0)     s[nf][0] = -10000.0f;
                if (c + 1 > grow0)     s[nf][1] = -10000.0f;
                if (c     > grow0 + 8) s[nf][2] = -10000.0f;
                if (c + 1 > grow0 + 8) s[nf][3] = -10000.0f;
            }
        }

        float rm0 = s[0][0], rm1 = s[0][2];
#pragma unroll
        for (int nf = 0; nf < 8; ++nf) {
            rm0 = fmaxf(rm0, fmaxf(s[nf][0], s[nf][1]));
            rm1 = fmaxf(rm1, fmaxf(s[nf][2], s[nf][3]));
        }
        rm0 = fmaxf(rm0, __shfl_xor_sync(0xffffffffu, rm0, 1));
        rm0 = fmaxf(rm0, __shfl_xor_sync(0xffffffffu, rm0, 2));
        rm1 = fmaxf(rm1, __shfl_xor_sync(0xffffffffu, rm1, 1));
        rm1 = fmaxf(rm1, __shfl_xor_sync(0xffffffffu, rm1, 2));

        const float mn0 = fmaxf(m_i[0], rm0);
        const float mn1 = fmaxf(m_i[1], rm1);
        const float alpha0 = __expf(m_i[0] - mn0);
        const float alpha1 = __expf(m_i[1] - mn1);
        m_i[0] = mn0; m_i[1] = mn1;

        float ls0 = 0.0f, ls1 = 0.0f;
        uint32_t ph0[8], ph1[8];
#pragma unroll
        for (int nf = 0; nf < 8; ++nf) {
            float p0 = __expf(s[nf][0] - mn0);
            float p1 = __expf(s[nf][1] - mn0);
            float p2 = __expf(s[nf][2] - mn1);
            float p3 = __expf(s[nf][3] - mn1);
            ls0 += p0 + p1;
            ls1 += p2 + p3;
            ph0[nf] = pack_h2(p0, p1);
            ph1[nf] = pack_h2(p2, p3);
        }
        ls0 += __shfl_xor_sync(0xffffffffu, ls0, 1);
        ls0 += __shfl_xor_sync(0xffffffffu, ls0, 2);
        ls1 += __shfl_xor_sync(0xffffffffu, ls1, 1);
        ls1 += __shfl_xor_sync(0xffffffffu, ls1, 2);

        l_i[0] = l_i[0] * alpha0 + ls0;
        l_i[1] = l_i[1] * alpha1 + ls1;
#pragma unroll
        for (int nf = 0; nf < 8; ++nf) {
            O[nf][0] *= alpha0; O[nf][1] *= alpha0;
            O[nf][2] *= alpha1; O[nf][3] *= alpha1;
        }

#pragma unroll
        for (int c = 0; c < 4; ++c) {
            uint32_t af[4] = {ph0[2 * c], ph1[2 * c], ph0[2 * c + 1], ph1[2 * c + 1]};
#pragma unroll
            for (int nf2 = 0; nf2 < 4; ++nf2) {
                const int g2 = lane >> 3;
                const int vrow = c * 16 + ((g2 & 1) ? 8 : 0) + (lane & 7);
                const int vcol = nf2 * 8 + ((g2 >> 1) ? 4 : 0);
                uint32_t vb[4];
                ldmatrix_x4t(vb, vbase + (vrow * 36 + vcol) * 4);
                mma_f16(O[2 * nf2],     af, vb);
                mma_f16(O[2 * nf2 + 1], af, vb + 2);
            }
        }
    }

    const float inv0 = 1.0f / l_i[0];
    const float inv1 = 1.0f / l_i[1];
#pragma unroll
    for (int nf = 0; nf < 8; ++nf) {
        b_a[(qrow0 + r0) * 512 + h * 32 + nf * 4 + tg] =
            pack_h2(O[nf][0] * inv0, O[nf][1] * inv0);
        b_a[(qrow0 + r1) * 512 + h * 32 + nf * 4 + tg] =
            pack_h2(O[nf][2] * inv1, O[nf][3] * inv1);
    }
}

// ---------------------------------------------------------------------------
// Launch
// ---------------------------------------------------------------------------
extern "C" void kernel_launch(void* const* d_in, const int* in_sizes, int n_in,
                              void* d_out, int out_size)
{
    const float* x     = (const float*)d_in[0];
    const float* query = (const float*)d_in[1];
    const float* attw  = (const float*)d_in[2];
    const float* attb  = (const float*)d_in[3];
    const float* projw = (const float*)d_in[4];
    const float* projb = (const float*)d_in[5];
    float* out = (float*)d_out;

    cudaFuncSetAttribute(qkv_gemm_kernel,
                         cudaFuncAttributeMaxDynamicSharedMemorySize, GEMM_DYN);
    cudaFuncSetAttribute(proj_gemm_kernel,
                         cudaFuncAttributeMaxDynamicSharedMemorySize, GEMM_DYN);
    cudaFuncSetAttribute(attn_kernel,
                         cudaFuncAttributeMaxDynamicSharedMemorySize, ATT_DYN);

    // fused pre-pass: fp16 conversion + weight pack (one launch)
    prepass_kernel<<<6144, 256>>>((const float4*)query, (const float4*)x,
                                  attw, projw);

    // q/k/v projections
    qkv_gemm_kernel<<<dim3(24, 64), 256, GEMM_DYN>>>(attb);

    // attention
    attn_kernel<<<dim3(8, NH, BSZ), 256, ATT_DYN>>>();

    // output projection
    proj_gemm_kernel<<<dim3(8, 64), 256, GEMM_DYN>>>(projb, out);
}

// round 17
// speedup vs baseline: 1.5107x; 1.5107x over previous
#include <cuda_runtime.h>
#include <cuda_fp16.h>
#include <cstdint>

// Problem constants
#define BSZ 8
#define SEQ 1024
#define NX  1024
#define NH  16
#define HD  64

// All half-precision buffers stored as uint32 words (2 halves per word)
__device__ uint32_t b_inq[8192 * 512];   // query, fp16
__device__ uint32_t b_inx[8192 * 512];   // x, fp16
__device__ uint32_t b_w2[512 * 3072];    // attw packed: [k2][n], word=(k even, k odd)
__device__ uint32_t b_p2[512 * 1024];    // projw packed
__device__ uint32_t b_q[8192 * 512];     // q*0.125, fp16
__device__ uint32_t b_k[8192 * 512];
__device__ uint32_t b_v[8192 * 512];
__device__ uint32_t b_a[8192 * 512];     // attention out, fp16

// ---------------------------------------------------------------------------
// helpers
// ---------------------------------------------------------------------------
__device__ __forceinline__ uint32_t pack_h2(float lo, float hi) {
    uint32_t d;
    asm("cvt.rn.f16x2.f32 %0, %1, %2;" : "=r"(d) : "f"(hi), "f"(lo));
    return d;
}
__device__ __forceinline__ void mma_f16(float c[4], const uint32_t a[4],
                                        const uint32_t b[2]) {
    asm volatile(
        "mma.sync.aligned.m16n8k16.row.col.f32.f16.f16.f32 "
        "{%0,%1,%2,%3}, {%4,%5,%6,%7}, {%8,%9}, {%0,%1,%2,%3};\n"
        : "+f"(c[0]), "+f"(c[1]), "+f"(c[2]), "+f"(c[3])
        : "r"(a[0]), "r"(a[1]), "r"(a[2]), "r"(a[3]), "r"(b[0]), "r"(b[1]));
}
__device__ __forceinline__ void ldmatrix_x4(uint32_t r[4], uint32_t addr) {
    asm volatile("ldmatrix.sync.aligned.m8n8.x4.shared.b16 {%0,%1,%2,%3}, [%4];"
                 : "=r"(r[0]), "=r"(r[1]), "=r"(r[2]), "=r"(r[3]) : "r"(addr));
}
__device__ __forceinline__ void ldmatrix_x4t(uint32_t r[4], uint32_t addr) {
    asm volatile("ldmatrix.sync.aligned.m8n8.x4.trans.shared.b16 {%0,%1,%2,%3}, [%4];"
                 : "=r"(r[0]), "=r"(r[1]), "=r"(r[2]), "=r"(r[3]) : "r"(addr));
}
__device__ __forceinline__ void cpa16(uint32_t dst, const void* src) {
    asm volatile("cp.async.cg.shared.global [%0], [%1], 16;" :: "r"(dst), "l"(src));
}
__device__ __forceinline__ uint32_t smem_u32(const void* p) {
    uint32_t a;
    asm("{ .reg .u64 t; cvta.to.shared.u64 t, %1; cvt.u32.u64 %0, t; }"
        : "=r"(a) : "l"(p));
    return a;
}

// ---------------------------------------------------------------------------
// fused pre-pass: fp16 convert (q, x) + weight pack (attw, projw)
// conv: 4096 blocks (4 float4/thread); attw pack: 1536; projw pack: 512.
// ---------------------------------------------------------------------------
__global__ __launch_bounds__(256) void prepass_kernel(
    const float4* __restrict__ q, const float4* __restrict__ x,
    const float* __restrict__ attw, const float* __restrict__ projw)
{
    const int blk = blockIdx.x;
    const int tid = threadIdx.x;
    if (blk < 4096) {
        const bool isq = blk < 2048;
        const size_t base = (size_t)(isq ? blk : blk - 2048) * 1024;
        const float4* src = isq ? q : x;
        uint32_t* o = isq ? b_inq : b_inx;
#pragma unroll
        for (int rr = 0; rr < 4; ++rr) {
            const size_t i = base + tid + rr * 256;
            const float4 f = src[i];
            o[2 * i]     = pack_h2(f.x, f.y);
            o[2 * i + 1] = pack_h2(f.z, f.w);
        }
    } else if (blk < 5632) {
        const int idx = blk - 4096;
        const int n4 = (idx % 3) * 256 + tid;
        const int k2 = idx / 3;
        const float4 e = *(const float4*)(attw + (size_t)(2 * k2) * 3072 + 4 * n4);
        const float4 o = *(const float4*)(attw + (size_t)(2 * k2 + 1) * 3072 + 4 * n4);
        uint4 r;
        r.x = pack_h2(e.x, o.x); r.y = pack_h2(e.y, o.y);
        r.z = pack_h2(e.z, o.z); r.w = pack_h2(e.w, o.w);
        *(uint4*)(b_w2 + (size_t)k2 * 3072 + 4 * n4) = r;
    } else {
        const int k2 = blk - 5632;
        const int n4 = tid;
        const float4 e = *(const float4*)(projw + (size_t)(2 * k2) * 1024 + 4 * n4);
        const float4 o = *(const float4*)(projw + (size_t)(2 * k2 + 1) * 1024 + 4 * n4);
        uint4 r;
        r.x = pack_h2(e.x, o.x); r.y = pack_h2(e.y, o.y);
        r.z = pack_h2(e.z, o.z); r.w = pack_h2(e.w, o.w);
        *(uint4*)(b_p2 + (size_t)k2 * 1024 + 4 * n4) = r;
    }
}

// ---------------------------------------------------------------------------
// fp16 GEMM mainloop: CTA 128x128, 256 thr = 8 warps (2m x 4n), warp 64x32.
// 3-stage cp.async pipeline (wait_group 1), ldmatrix.x4 A fragments.
// ---------------------------------------------------------------------------
#define AW 36
#define BW 136
#define STW (128 * AW + 32 * BW)          // words per stage = 8960
#define NST 3
#define GEMM_DYN (NST * STW * 4)          // 107520 bytes

__device__ __forceinline__ void gemm16_main(
    const uint32_t* __restrict__ Ag, const uint32_t* __restrict__ Wg,
    int ldw2, int m0, int ng, float acc[4][4][4])
{
    extern __shared__ __align__(16) uint32_t smw[];
    const uint32_t sbase = smem_u32(smw);

    const int t = threadIdx.x;
    const int lane = t & 31;
    const int warp = t >> 5;
    const int gid = lane >> 2, tg = lane & 3;
    const int wm = (warp & 1) * 64, wn = (warp >> 1) * 32;
    const int sr = t >> 3;
    const int si = (t & 7) * 4;

#pragma unroll
    for (int i = 0; i < 4; ++i)
#pragma unroll
        for (int j = 0; j < 4; ++j)
#pragma unroll
            for (int r = 0; r < 4; ++r) acc[i][j][r] = 0.0f;

    auto load_stage = [&](int kt, int st) {
        const uint32_t sa = sbase + (st * STW) * 4;
        const uint32_t sb = sa + (128 * AW) * 4;
#pragma unroll
        for (int rr = 0; rr < 4; ++rr)
            cpa16(sa + ((sr + rr * 32) * AW + si) * 4,
                  Ag + (size_t)(m0 + sr + rr * 32) * 512 + kt * 32 + si);
#pragma unroll
        for (int ii = 0; ii < 2; ++ii) {
            const int id = t + ii * 256;
            const int brow = id >> 5;
            const int bcol = (id & 31) * 4;
            cpa16(sb + (brow * BW + bcol) * 4,
                  Wg + (size_t)(kt * 32 + brow) * ldw2 + ng + bcol);
        }
#pragma unroll
        for (int ii = 0; ii < 2; ++ii) {
            const int id = t + ii * 256;
            const int brow = (id >> 5) + 16;
            const int bcol = (id & 31) * 4;
            cpa16(sb + (brow * BW + bcol) * 4,
                  Wg + (size_t)(kt * 32 + brow) * ldw2 + ng + bcol);
        }
        asm volatile("cp.async.commit_group;" ::: "memory");
    };

    load_stage(0, 0);
    load_stage(1, 1);

    for (int kt = 0; kt < 16; ++kt) {
        const int cur = kt % NST;
        asm volatile("cp.async.wait_group 1;" ::: "memory");
        __syncthreads();
        if (kt + 2 < 16) load_stage(kt + 2, (kt + 2) % NST);

        const uint32_t sa = sbase + (cur * STW) * 4;
        const uint32_t* Bs = smw + cur * STW + 128 * AW;
        const uint32_t arow = (uint32_t)(lane & 15);
        const uint32_t ahalf = (uint32_t)(lane >> 4) * 4;

#pragma unroll
        for (int c = 0; c < 4; ++c) {
            uint32_t afr[4][4], bfr[4][2];
#pragma unroll
            for (int mf = 0; mf < 4; ++mf)
                ldmatrix_x4(afr[mf],
                    sa + ((wm + mf * 16 + arow) * AW + c * 8 + ahalf) * 4);
#pragma unroll
            for (int nf = 0; nf < 4; ++nf) {
                const int n = wn + nf * 8 + gid;
                bfr[nf][0] = Bs[(c * 8 + tg) * BW + n];
                bfr[nf][1] = Bs[(c * 8 + tg + 4) * BW + n];
            }
#pragma unroll
            for (int mf = 0; mf < 4; ++mf)
#pragma unroll
                for (int nf = 0; nf < 4; ++nf)
                    mma_f16(acc[mf][nf], afr[mf], bfr[nf]);
        }
    }
}

// qkv projection: grid (24, 64). Writes q/k/v as fp16 (q pre-scaled 0.125).
__global__ __launch_bounds__(256) void qkv_gemm_kernel(const float* __restrict__ bias)
{
    const int ng = blockIdx.x * 128;
    const int m0 = blockIdx.y * 128;
    const uint32_t* Ag = (ng < 1024) ? b_inq : b_inx;
    float acc[4][4][4];
    gemm16_main(Ag, b_w2, 3072, m0, ng, acc);

    const int t = threadIdx.x;
    const int lane = t & 31, warp = t >> 5;
    const int gid = lane >> 2, tg = lane & 3;
    const int wm = (warp & 1) * 64, wn = (warp >> 1) * 32;

    uint32_t* Og; int ccol; float scale;
    if (ng < 1024)       { Og = b_q; ccol = ng;        scale = 0.125f; }
    else if (ng < 2048)  { Og = b_k; ccol = ng - 1024; scale = 1.0f; }
    else                 { Og = b_v; ccol = ng - 2048; scale = 1.0f; }

#pragma unroll
    for (int nf = 0; nf < 4; ++nf) {
        const int cl = wn + nf * 8 + 2 * tg;
        const float b0 = bias[ng + cl], b1 = bias[ng + cl + 1];
#pragma unroll
        for (int mf = 0; mf < 4; ++mf) {
            const int row = m0 + wm + mf * 16 + gid;
            Og[(size_t)row * 512 + (ccol + cl) / 2] =
                pack_h2((acc[mf][nf][0] + b0) * scale,
                        (acc[mf][nf][1] + b1) * scale);
            Og[(size_t)(row + 8) * 512 + (ccol + cl) / 2] =
                pack_h2((acc[mf][nf][2] + b0) * scale,
                        (acc[mf][nf][3] + b1) * scale);
        }
    }
}

// output projection: grid (8, 64). Reads b_a (fp16), writes f32 out.
__global__ __launch_bounds__(256) void proj_gemm_kernel(
    const float* __restrict__ bias, float* __restrict__ out)
{
    const int ng = blockIdx.x * 128;
    const int m0 = blockIdx.y * 128;
    float acc[4][4][4];
    gemm16_main(b_a, b_p2, 1024, m0, ng, acc);

    const int t = threadIdx.x;
    const int lane = t & 31, warp = t >> 5;
    const int gid = lane >> 2, tg = lane & 3;
    const int wm = (warp & 1) * 64, wn = (warp >> 1) * 32;

#pragma unroll
    for (int nf = 0; nf < 4; ++nf) {
        const int cl = wn + nf * 8 + 2 * tg;
        const float b0 = bias[ng + cl], b1 = bias[ng + cl + 1];
#pragma unroll
        for (int mf = 0; mf < 4; ++mf) {
            const int row = m0 + wm + mf * 16 + gid;
            *(float2*)(out + (size_t)row * 1024 + ng + cl) =
                make_float2(acc[mf][nf][0] + b0, acc[mf][nf][1] + b1);
            *(float2*)(out + (size_t)(row + 8) * 1024 + ng + cl) =
                make_float2(acc[mf][nf][2] + b0, acc[mf][nf][3] + b1);
        }
    }
}

// ---------------------------------------------------------------------------
// fp16 flash attention, 3-stage cp.async K/V pipeline (wait_group 1).
// Grid (8, 16, 8), 256 thr (8 warps x 16 q-rows).
// Heavy diagonals first: qb = 7 - blockIdx.x (tail balance).
// ---------------------------------------------------------------------------
#define QW   (128 * 36)
#define KVW  (64 * 36)
#define ANST 3
#define ATT_DYN ((QW + ANST * 2 * KVW) * 4)   // 73728 bytes

__global__ __launch_bounds__(256) void attn_kernel()
{
    extern __shared__ __align__(16) uint32_t sma[];
    const uint32_t sbase = smem_u32(sma);

    const int qb = 7 - blockIdx.x;        // heavy tiles scheduled first
    const int h = blockIdx.y, b = blockIdx.z;
    const int t = threadIdx.x;
    const int warp = t >> 5, lane = t & 31;
    const int gid = lane >> 2, tg = lane & 3;
    const int r0 = warp * 16 + gid, r1 = r0 + 8;
    const size_t qrow0 = (size_t)(b * SEQ + qb * 128);
    const size_t kvbase = (size_t)(b * SEQ) * 512 + h * 32;

    auto load_kv = [&](int kb, int st) {
        const uint32_t kdst = sbase + (QW + st * 2 * KVW) * 4;
        const uint32_t vdst = kdst + KVW * 4;
#pragma unroll
        for (int i = 0; i < 2; ++i) {
            const int id = t + i * 256;
            const int row = id >> 3;
            const int cq = (id & 7) * 4;
            const size_t g = kvbase + (size_t)(kb * 64 + row) * 512 + cq;
            cpa16(kdst + (row * 36 + cq) * 4, b_k + g);
            cpa16(vdst + (row * 36 + cq) * 4, b_v + g);
        }
        asm volatile("cp.async.commit_group;" ::: "memory");
    };

    const int nkb = 2 * qb + 2;           // >= 2 always

    // prologue: two K/V stages in flight, then stage Q
    load_kv(0, 0);
    load_kv(1, 1);
    {
        const int sr = t >> 3, si = (t & 7) * 4;
#pragma unroll
        for (int rr = 0; rr < 4; ++rr) {
            uint4 v = *(const uint4*)(b_q + (qrow0 + sr + rr * 32) * 512
                                      + h * 32 + si);
            *(uint4*)&sma[(sr + rr * 32) * 36 + si] = v;
        }
    }
    __syncthreads();

    uint32_t qf[4][4];
#pragma unroll
    for (int c = 0; c < 4; ++c) {
        qf[c][0] = sma[r0 * 36 + c * 8 + tg];
        qf[c][1] = sma[r1 * 36 + c * 8 + tg];
        qf[c][2] = sma[r0 * 36 + c * 8 + tg + 4];
        qf[c][3] = sma[r1 * 36 + c * 8 + tg + 4];
    }

    float m_i[2] = {-3.0e38f, -3.0e38f};
    float l_i[2] = {0.0f, 0.0f};
    float O[8][4];
#pragma unroll
    for (int nf = 0; nf < 8; ++nf)
#pragma unroll
        for (int r = 0; r < 4; ++r) O[nf][r] = 0.0f;

    for (int kb = 0; kb < nkb; ++kb) {
        const int st = kb % ANST;
        // last iteration has only kb+1 groups committed -> must drain fully
        if (kb + 1 < nkb)
            asm volatile("cp.async.wait_group 1;" ::: "memory");
        else
            asm volatile("cp.async.wait_group 0;" ::: "memory");
        __syncthreads();
        if (kb + 2 < nkb) load_kv(kb + 2, (kb + 2) % ANST);

        const uint32_t* Ks = sma + QW + st * 2 * KVW;
        const uint32_t vbase = sbase + (QW + st * 2 * KVW + KVW) * 4;

        float s[8][4];
#pragma unroll
        for (int nf = 0; nf < 8; ++nf)
#pragma unroll
            for (int r = 0; r < 4; ++r) s[nf][r] = 0.0f;
#pragma unroll
        for (int c = 0; c < 4; ++c)
#pragma unroll
            for (int nf = 0; nf < 8; ++nf) {
                uint32_t bb[2];
                const int key = nf * 8 + gid;
                bb[0] = Ks[key * 36 + c * 8 + tg];
                bb[1] = Ks[key * 36 + c * 8 + tg + 4];
                mma_f16(s[nf], qf[c], bb);
            }

        if (kb >= 2 * qb) {
            const int grow0 = qb * 128 + r0;
            const int gcol0 = kb * 64 + 2 * tg;
#pragma unroll
            for (int nf = 0; nf < 8; ++nf) {
                int c = gcol0 + nf * 8;
                if (c     > grow0)     s[nf][0] = -10000.0f;
                if (c + 1 > grow0)     s[nf][1] = -10000.0f;
                if (c     > grow0 + 8) s[nf][2] = -10000.0f;
                if (c + 1 > grow0 + 8) s[nf][3] = -10000.0f;
            }
        }

        float rm0 = s[0][0], rm1 = s[0][2];
#pragma unroll
        for (int nf = 0; nf < 8; ++nf) {
            rm0 = fmaxf(rm0, fmaxf(s[nf][0], s[nf][1]));
            rm1 = fmaxf(rm1, fmaxf(s[nf][2], s[nf][3]));
        }
        rm0 = fmaxf(rm0, __shfl_xor_sync(0xffffffffu, rm0, 1));
        rm0 = fmaxf(rm0, __shfl_xor_sync(0xffffffffu, rm0, 2));
        rm1 = fmaxf(rm1, __shfl_xor_sync(0xffffffffu, rm1, 1));
        rm1 = fmaxf(rm1, __shfl_xor_sync(0xffffffffu, rm1, 2));

        const float mn0 = fmaxf(m_i[0], rm0);
        const float mn1 = fmaxf(m_i[1], rm1);
        const float alpha0 = __expf(m_i[0] - mn0);
        const float alpha1 = __expf(m_i[1] - mn1);
        m_i[0] = mn0; m_i[1] = mn1;

        float ls0 = 0.0f, ls1 = 0.0f;
        uint32_t ph0[8], ph1[8];
#pragma unroll
        for (int nf = 0; nf < 8; ++nf) {
            float p0 = __expf(s[nf][0] - mn0);
            float p1 = __expf(s[nf][1] - mn0);
            float p2 = __expf(s[nf][2] - mn1);
            float p3 = __expf(s[nf][3] - mn1);
            ls0 += p0 + p1;
            ls1 += p2 + p3;
            ph0[nf] = pack_h2(p0, p1);
            ph1[nf] = pack_h2(p2, p3);
        }
        ls0 += __shfl_xor_sync(0xffffffffu, ls0, 1);
        ls0 += __shfl_xor_sync(0xffffffffu, ls0, 2);
        ls1 += __shfl_xor_sync(0xffffffffu, ls1, 1);
        ls1 += __shfl_xor_sync(0xffffffffu, ls1, 2);

        l_i[0] = l_i[0] * alpha0 + ls0;
        l_i[1] = l_i[1] * alpha1 + ls1;
#pragma unroll
        for (int nf = 0; nf < 8; ++nf) {
            O[nf][0] *= alpha0; O[nf][1] *= alpha0;
            O[nf][2] *= alpha1; O[nf][3] *= alpha1;
        }

#pragma unroll
        for (int c = 0; c < 4; ++c) {
            uint32_t af[4] = {ph0[2 * c], ph1[2 * c], ph0[2 * c + 1], ph1[2 * c + 1]};
#pragma unroll
            for (int nf2 = 0; nf2 < 4; ++nf2) {
                const int g2 = lane >> 3;
                const int vrow = c * 16 + ((g2 & 1) ? 8 : 0) + (lane & 7);
                const int vcol = nf2 * 8 + ((g2 >> 1) ? 4 : 0);
                uint32_t vb[4];
                ldmatrix_x4t(vb, vbase + (vrow * 36 + vcol) * 4);
                mma_f16(O[2 * nf2],     af, vb);
                mma_f16(O[2 * nf2 + 1], af, vb + 2);
            }
        }
    }

    const float inv0 = 1.0f / l_i[0];
    const float inv1 = 1.0f / l_i[1];
#pragma unroll
    for (int nf = 0; nf < 8; ++nf) {
        b_a[(qrow0 + r0) * 512 + h * 32 + nf * 4 + tg] =
            pack_h2(O[nf][0] * inv0, O[nf][1] * inv0);
        b_a[(qrow0 + r1) * 512 + h * 32 + nf * 4 + tg] =
            pack_h2(O[nf][2] * inv1, O[nf][3] * inv1);
    }
}

// ---------------------------------------------------------------------------
// Launch
// ---------------------------------------------------------------------------
extern "C" void kernel_launch(void* const* d_in, const int* in_sizes, int n_in,
                              void* d_out, int out_size)
{
    const float* x     = (const float*)d_in[0];
    const float* query = (const float*)d_in[1];
    const float* attw  = (const float*)d_in[2];
    const float* attb  = (const float*)d_in[3];
    const float* projw = (const float*)d_in[4];
    const float* projb = (const float*)d_in[5];
    float* out = (float*)d_out;

    cudaFuncSetAttribute(qkv_gemm_kernel,
                         cudaFuncAttributeMaxDynamicSharedMemorySize, GEMM_DYN);
    cudaFuncSetAttribute(proj_gemm_kernel,
                         cudaFuncAttributeMaxDynamicSharedMemorySize, GEMM_DYN);
    cudaFuncSetAttribute(attn_kernel,
                         cudaFuncAttributeMaxDynamicSharedMemorySize, ATT_DYN);

    // fused pre-pass: fp16 conversion + weight pack (one launch)
    prepass_kernel<<<6144, 256>>>((const float4*)query, (const float4*)x,
                                  attw, projw);

    // q/k/v projections
    qkv_gemm_kernel<<<dim3(24, 64), 256, GEMM_DYN>>>(attb);

    // attention
    attn_kernel<<<dim3(8, NH, BSZ), 256, ATT_DYN>>>();

    // output projection
    proj_gemm_kernel<<<dim3(8, 64), 256, GEMM_DYN>>>(projb, out);
}